// round 1
// baseline (speedup 1.0000x reference)
#include <cuda_runtime.h>
#include <cstdint>

#define Nn  8192
#define IND 128
#define HID 32
#define BM  32
#define BK  64

// Scratch (no allocations allowed)
__device__ float g_dinv[Nn];
__device__ float g_zs[Nn * HID];
__device__ float g_h[Nn * HID];

// ---------------------------------------------------------------------------
// 1) degree: dinv[i] = rsqrt(max(1, 1 + sum_j adj[i,j]))
// ---------------------------------------------------------------------------
__global__ __launch_bounds__(256) void degree_kernel(const float* __restrict__ adj) {
    int row = blockIdx.x;
    const float4* rp = reinterpret_cast<const float4*>(adj + (size_t)row * Nn);
    float s = 0.f;
    for (int i = threadIdx.x; i < Nn / 4; i += 256) {
        float4 v = rp[i];
        s += (v.x + v.y) + (v.z + v.w);
    }
#pragma unroll
    for (int o = 16; o; o >>= 1) s += __shfl_down_sync(0xffffffffu, s, o);
    __shared__ float ws[8];
    int lane = threadIdx.x & 31, w = threadIdx.x >> 5;
    if (lane == 0) ws[w] = s;
    __syncthreads();
    if (threadIdx.x == 0) {
        float d = 1.0f;  // self loop
#pragma unroll
        for (int i = 0; i < 8; i++) d += ws[i];
        d = fmaxf(d, 1.0f);
        g_dinv[row] = rsqrtf(d);
    }
}

// ---------------------------------------------------------------------------
// 2) zs = dinv ⊙ (x @ W1 + b1)    [8192,128]x[128,32]
// ---------------------------------------------------------------------------
__global__ __launch_bounds__(256) void z1_kernel(const float* __restrict__ x,
                                                 const float* __restrict__ W1,
                                                 const float* __restrict__ b1) {
    __shared__ float Ws[IND * HID];
    __shared__ float xs[8][IND];
    int tid = threadIdx.x;
    int row0 = blockIdx.x * 8;
    for (int i = tid; i < IND * HID; i += 256) Ws[i] = W1[i];
    for (int i = tid; i < 8 * IND; i += 256)
        xs[i >> 7][i & 127] = x[(size_t)(row0 + (i >> 7)) * IND + (i & 127)];
    __syncthreads();
    int r = tid >> 5, c = tid & 31;
    float acc = b1[c];
#pragma unroll 8
    for (int k = 0; k < IND; k++) acc += xs[r][k] * Ws[k * HID + c];
    int row = row0 + r;
    g_zs[row * HID + c] = g_dinv[row] * acc;
}

// ---------------------------------------------------------------------------
// 4) zs = dinv ⊙ (h @ W2 + b2)    [8192,32]x[32,32]
// ---------------------------------------------------------------------------
__global__ __launch_bounds__(256) void z2_kernel(const float* __restrict__ W2,
                                                 const float* __restrict__ b2) {
    __shared__ float Ws[HID * HID];
    __shared__ float hs[8][HID];
    int tid = threadIdx.x;
    int row0 = blockIdx.x * 8;
    for (int i = tid; i < HID * HID; i += 256) Ws[i] = W2[i];
    for (int i = tid; i < 8 * HID; i += 256)
        hs[i >> 5][i & 31] = g_h[(size_t)(row0 + (i >> 5)) * HID + (i & 31)];
    __syncthreads();
    int r = tid >> 5, c = tid & 31;
    float acc = b2[c];
#pragma unroll
    for (int k = 0; k < HID; k++) acc += hs[r][k] * Ws[k * HID + c];
    int row = row0 + r;
    g_zs[row * HID + c] = g_dinv[row] * acc;
}

// ---------------------------------------------------------------------------
// 3+5) h = relu(dinv ⊙ (adj @ zs + zs))   -- the big GEMM, f32x2 packed FMA
//      reads g_zs, writes g_h. BM=32 rows/block, 128 threads, 8 cols/thread.
// ---------------------------------------------------------------------------
__global__ __launch_bounds__(128) void spmm_kernel(const float* __restrict__ adj) {
    __shared__ float As[BM][BK + 1];       // stride 65 (odd -> conflict-free col reads)
    __shared__ float Bs[BK][HID + 4];      // stride 36 (16B aligned rows)
    int tid = threadIdx.x;
    int row0 = blockIdx.x * BM;
    int r = tid & 31;        // row within tile (lane)
    int cg = tid >> 5;       // 0..3 column group
    int c0 = cg * 8;

    unsigned long long acc0 = 0, acc1 = 0, acc2 = 0, acc3 = 0;

    for (int kt = 0; kt < Nn; kt += BK) {
        // load adj tile [BM][BK] : 512 float4, 4 per thread (coalesced 128B/warp-row)
#pragma unroll
        for (int i = tid; i < BM * BK / 4; i += 128) {
            int rr = i >> 4;
            int k4 = (i & 15) << 2;
            float4 v = *reinterpret_cast<const float4*>(
                &adj[(size_t)(row0 + rr) * Nn + kt + k4]);
            As[rr][k4 + 0] = v.x; As[rr][k4 + 1] = v.y;
            As[rr][k4 + 2] = v.z; As[rr][k4 + 3] = v.w;
        }
        // load zs tile [BK][32]
#pragma unroll
        for (int i = tid; i < BK * HID / 4; i += 128) {
            int rr = i >> 3;
            int c4 = (i & 7) << 2;
            float4 v = *reinterpret_cast<const float4*>(&g_zs[(size_t)(kt + rr) * HID + c4]);
            *reinterpret_cast<float4*>(&Bs[rr][c4]) = v;
        }
        __syncthreads();

#pragma unroll 16
        for (int kk = 0; kk < BK; kk++) {
            float a = As[r][kk];
            unsigned long long aa;
            asm("mov.b64 %0, {%1,%1};" : "=l"(aa) : "f"(a));
            const unsigned long long* bp =
                reinterpret_cast<const unsigned long long*>(&Bs[kk][c0]);
            unsigned long long b0 = bp[0], b1v = bp[1], b2v = bp[2], b3v = bp[3];
            asm("fma.rn.f32x2 %0, %1, %2, %0;" : "+l"(acc0) : "l"(aa), "l"(b0));
            asm("fma.rn.f32x2 %0, %1, %2, %0;" : "+l"(acc1) : "l"(aa), "l"(b1v));
            asm("fma.rn.f32x2 %0, %1, %2, %0;" : "+l"(acc2) : "l"(aa), "l"(b2v));
            asm("fma.rn.f32x2 %0, %1, %2, %0;" : "+l"(acc3) : "l"(aa), "l"(b3v));
        }
        __syncthreads();
    }

    float o[8];
    asm("mov.b64 {%0,%1}, %2;" : "=f"(o[0]), "=f"(o[1]) : "l"(acc0));
    asm("mov.b64 {%0,%1}, %2;" : "=f"(o[2]), "=f"(o[3]) : "l"(acc1));
    asm("mov.b64 {%0,%1}, %2;" : "=f"(o[4]), "=f"(o[5]) : "l"(acc2));
    asm("mov.b64 {%0,%1}, %2;" : "=f"(o[6]), "=f"(o[7]) : "l"(acc3));

    int row = row0 + r;
    float di = g_dinv[row];
#pragma unroll
    for (int j = 0; j < 8; j++) {
        float v = di * (o[j] + g_zs[row * HID + c0 + j]);  // + self loop, normalize
        g_h[row * HID + c0 + j] = fmaxf(v, 0.f);           // relu
    }
}

// ---------------------------------------------------------------------------
// 6) logits[i] = h[i,:] @ W3 + b3   (warp per row)
// ---------------------------------------------------------------------------
__global__ __launch_bounds__(256) void final_kernel(const float* __restrict__ W3,
                                                    const float* __restrict__ b3,
                                                    float* __restrict__ out) {
    int tid = threadIdx.x;
    int row = blockIdx.x * 8 + (tid >> 5);
    int c = tid & 31;
    float v = g_h[row * HID + c] * W3[c];
#pragma unroll
    for (int o = 16; o; o >>= 1) v += __shfl_down_sync(0xffffffffu, v, o);
    if (c == 0) out[row] = v + b3[0];
}

// ---------------------------------------------------------------------------
extern "C" void kernel_launch(void* const* d_in, const int* in_sizes, int n_in,
                              void* d_out, int out_size) {
    const float* x   = (const float*)d_in[0];
    const float* adj = (const float*)d_in[1];
    const float* W1  = (const float*)d_in[2];
    const float* b1  = (const float*)d_in[3];
    const float* W2  = (const float*)d_in[4];
    const float* b2  = (const float*)d_in[5];
    const float* W3  = (const float*)d_in[6];
    const float* b3  = (const float*)d_in[7];
    float* out = (float*)d_out;

    degree_kernel<<<Nn, 256>>>(adj);
    z1_kernel<<<Nn / 8, 256>>>(x, W1, b1);
    spmm_kernel<<<Nn / BM, 128>>>(adj);   // layer 1: g_zs -> g_h
    z2_kernel<<<Nn / 8, 256>>>(W2, b2);   // g_h -> g_zs
    spmm_kernel<<<Nn / BM, 128>>>(adj);   // layer 2: g_zs -> g_h
    final_kernel<<<Nn / 8, 256>>>(W3, b3, out);
}

// round 2
// speedup vs baseline: 2.5364x; 2.5364x over previous
#include <cuda_runtime.h>
#include <cstdint>

#define Nn     8192
#define IND    128
#define HID    32
#define BM     128
#define BK     32
#define KSPLIT 8
#define KCHUNK (Nn / KSPLIT)   // 1024

typedef unsigned long long u64;

// Scratch (no allocations allowed)
__device__ float g_dinv[Nn];
__device__ float g_zs[Nn * HID];
__device__ float g_h[Nn * HID];
__device__ float g_part[(size_t)KSPLIT * Nn * HID];   // 8 MB partials

// ---------------------------------------------------------------------------
// 1) degree: dinv[i] = rsqrt(max(1, 1 + sum_j adj[i,j]))
// ---------------------------------------------------------------------------
__global__ __launch_bounds__(256) void degree_kernel(const float* __restrict__ adj) {
    int row = blockIdx.x;
    const float4* rp = reinterpret_cast<const float4*>(adj + (size_t)row * Nn);
    float s = 0.f;
    for (int i = threadIdx.x; i < Nn / 4; i += 256) {
        float4 v = rp[i];
        s += (v.x + v.y) + (v.z + v.w);
    }
#pragma unroll
    for (int o = 16; o; o >>= 1) s += __shfl_down_sync(0xffffffffu, s, o);
    __shared__ float ws[8];
    int lane = threadIdx.x & 31, w = threadIdx.x >> 5;
    if (lane == 0) ws[w] = s;
    __syncthreads();
    if (threadIdx.x == 0) {
        float d = 1.0f;  // self loop
#pragma unroll
        for (int i = 0; i < 8; i++) d += ws[i];
        d = fmaxf(d, 1.0f);
        g_dinv[row] = rsqrtf(d);
    }
}

// ---------------------------------------------------------------------------
// 2) zs = dinv ⊙ (x @ W1 + b1)    [8192,128]x[128,32]
// ---------------------------------------------------------------------------
__global__ __launch_bounds__(256) void z1_kernel(const float* __restrict__ x,
                                                 const float* __restrict__ W1,
                                                 const float* __restrict__ b1) {
    __shared__ float Ws[IND * HID];
    __shared__ float xs[8][IND];
    int tid = threadIdx.x;
    int row0 = blockIdx.x * 8;
    for (int i = tid; i < IND * HID; i += 256) Ws[i] = W1[i];
    for (int i = tid; i < 8 * IND; i += 256)
        xs[i >> 7][i & 127] = x[(size_t)(row0 + (i >> 7)) * IND + (i & 127)];
    __syncthreads();
    int r = tid >> 5, c = tid & 31;
    float acc = b1[c];
#pragma unroll 8
    for (int k = 0; k < IND; k++) acc += xs[r][k] * Ws[k * HID + c];
    int row = row0 + r;
    g_zs[row * HID + c] = g_dinv[row] * acc;
}

// ---------------------------------------------------------------------------
// 4) zs = dinv ⊙ (h @ W2 + b2)    [8192,32]x[32,32]
// ---------------------------------------------------------------------------
__global__ __launch_bounds__(256) void z2_kernel(const float* __restrict__ W2,
                                                 const float* __restrict__ b2) {
    __shared__ float Ws[HID * HID];
    __shared__ float hs[8][HID];
    int tid = threadIdx.x;
    int row0 = blockIdx.x * 8;
    for (int i = tid; i < HID * HID; i += 256) Ws[i] = W2[i];
    for (int i = tid; i < 8 * HID; i += 256)
        hs[i >> 5][i & 31] = g_h[(size_t)(row0 + (i >> 5)) * HID + (i & 31)];
    __syncthreads();
    int r = tid >> 5, c = tid & 31;
    float acc = b2[c];
#pragma unroll
    for (int k = 0; k < HID; k++) acc += hs[r][k] * Ws[k * HID + c];
    int row = row0 + r;
    g_zs[row * HID + c] = g_dinv[row] * acc;
}

// ---------------------------------------------------------------------------
// 3+5) partials of adj @ zs : register-blocked 4 rows x 8 cols per thread,
//      f32x2 packed FMA, transposed conflict-free A tile, K-split into 8.
//      grid = (Nn/BM) * KSPLIT = 512 blocks, 128 threads.
// ---------------------------------------------------------------------------
__global__ __launch_bounds__(128) void spmm_kernel(const float* __restrict__ adj) {
    __shared__ float As[BK][BM + 1];     // transposed: As[k][row], stride 129
    __shared__ float Bs[BK][HID + 8];    // stride 40 floats (160B, 16B aligned rows)

    int tid = threadIdx.x;
    int mb  = blockIdx.x >> 3;           // M tile (64 of them)
    int ks  = blockIdx.x & (KSPLIT - 1); // K chunk
    int row0 = mb * BM;
    int k0   = ks * KCHUNK;
    int rg = tid & 31;                   // row slot: rows rg, rg+32, rg+64, rg+96
    int cg = tid >> 5;                   // column group (warp id)
    int c0 = cg * 8;

    u64 acc[4][4];
#pragma unroll
    for (int r = 0; r < 4; r++)
#pragma unroll
        for (int j = 0; j < 4; j++) acc[r][j] = 0ull;

    for (int kt = k0; kt < k0 + KCHUNK; kt += BK) {
        // A tile: 128 rows x 32 k = 1024 float4; 8 per thread, coalesced along k,
        // stored transposed (conflict-free with stride 129).
#pragma unroll
        for (int i = 0; i < 8; i++) {
            int idx = tid + i * 128;
            int rr = idx >> 3;
            int k4 = (idx & 7) << 2;
            float4 v = *reinterpret_cast<const float4*>(
                &adj[(size_t)(row0 + rr) * Nn + kt + k4]);
            As[k4 + 0][rr] = v.x;
            As[k4 + 1][rr] = v.y;
            As[k4 + 2][rr] = v.z;
            As[k4 + 3][rr] = v.w;
        }
        // B tile: 32 x 32 = 256 float4; 2 per thread
#pragma unroll
        for (int i = 0; i < 2; i++) {
            int idx = tid + i * 128;
            int rr = idx >> 3;
            int c4 = (idx & 7) << 2;
            *reinterpret_cast<float4*>(&Bs[rr][c4]) =
                *reinterpret_cast<const float4*>(&g_zs[(size_t)(kt + rr) * HID + c4]);
        }
        __syncthreads();

#pragma unroll 8
        for (int kk = 0; kk < BK; kk++) {
            const u64* bp = reinterpret_cast<const u64*>(&Bs[kk][c0]);
            u64 b0 = bp[0], b1 = bp[1], b2 = bp[2], b3 = bp[3];  // broadcast loads
#pragma unroll
            for (int r = 0; r < 4; r++) {
                float a = As[kk][rg + r * 32];                   // conflict-free LDS.32
                u64 aa;
                asm("mov.b64 %0, {%1,%1};" : "=l"(aa) : "f"(a));
                asm("fma.rn.f32x2 %0, %1, %2, %0;" : "+l"(acc[r][0]) : "l"(aa), "l"(b0));
                asm("fma.rn.f32x2 %0, %1, %2, %0;" : "+l"(acc[r][1]) : "l"(aa), "l"(b1));
                asm("fma.rn.f32x2 %0, %1, %2, %0;" : "+l"(acc[r][2]) : "l"(aa), "l"(b2));
                asm("fma.rn.f32x2 %0, %1, %2, %0;" : "+l"(acc[r][3]) : "l"(aa), "l"(b3));
            }
        }
        __syncthreads();
    }

    float* pp = g_part + (size_t)ks * Nn * HID;
#pragma unroll
    for (int r = 0; r < 4; r++) {
        int row = row0 + rg + r * 32;
        float o[8];
        asm("mov.b64 {%0,%1}, %2;" : "=f"(o[0]), "=f"(o[1]) : "l"(acc[r][0]));
        asm("mov.b64 {%0,%1}, %2;" : "=f"(o[2]), "=f"(o[3]) : "l"(acc[r][1]));
        asm("mov.b64 {%0,%1}, %2;" : "=f"(o[4]), "=f"(o[5]) : "l"(acc[r][2]));
        asm("mov.b64 {%0,%1}, %2;" : "=f"(o[6]), "=f"(o[7]) : "l"(acc[r][3]));
        float4 v0 = make_float4(o[0], o[1], o[2], o[3]);
        float4 v1 = make_float4(o[4], o[5], o[6], o[7]);
        *reinterpret_cast<float4*>(&pp[(size_t)row * HID + c0])     = v0;
        *reinterpret_cast<float4*>(&pp[(size_t)row * HID + c0 + 4]) = v1;
    }
}

// ---------------------------------------------------------------------------
// Epilogue: h = relu(dinv ⊙ (sum_k partials + zs))   (self loop fused)
// ---------------------------------------------------------------------------
__global__ __launch_bounds__(256) void epilogue_kernel() {
    int idx4 = blockIdx.x * 256 + threadIdx.x;   // float4 index over Nn*HID/4
    int row = (idx4 << 2) >> 5;                  // HID = 32
    float4 s = reinterpret_cast<const float4*>(g_zs)[idx4];
#pragma unroll
    for (int p = 0; p < KSPLIT; p++) {
        float4 v = reinterpret_cast<const float4*>(g_part + (size_t)p * Nn * HID)[idx4];
        s.x += v.x; s.y += v.y; s.z += v.z; s.w += v.w;
    }
    float di = g_dinv[row];
    float4 o;
    o.x = fmaxf(di * s.x, 0.f);
    o.y = fmaxf(di * s.y, 0.f);
    o.z = fmaxf(di * s.z, 0.f);
    o.w = fmaxf(di * s.w, 0.f);
    reinterpret_cast<float4*>(g_h)[idx4] = o;
}

// ---------------------------------------------------------------------------
// 6) logits[i] = h[i,:] @ W3 + b3   (warp per row)
// ---------------------------------------------------------------------------
__global__ __launch_bounds__(256) void final_kernel(const float* __restrict__ W3,
                                                    const float* __restrict__ b3,
                                                    float* __restrict__ out) {
    int tid = threadIdx.x;
    int row = blockIdx.x * 8 + (tid >> 5);
    int c = tid & 31;
    float v = g_h[row * HID + c] * W3[c];
#pragma unroll
    for (int o = 16; o; o >>= 1) v += __shfl_down_sync(0xffffffffu, v, o);
    if (c == 0) out[row] = v + b3[0];
}

// ---------------------------------------------------------------------------
extern "C" void kernel_launch(void* const* d_in, const int* in_sizes, int n_in,
                              void* d_out, int out_size) {
    const float* x   = (const float*)d_in[0];
    const float* adj = (const float*)d_in[1];
    const float* W1  = (const float*)d_in[2];
    const float* b1  = (const float*)d_in[3];
    const float* W2  = (const float*)d_in[4];
    const float* b2  = (const float*)d_in[5];
    const float* W3  = (const float*)d_in[6];
    const float* b3  = (const float*)d_in[7];
    float* out = (float*)d_out;

    degree_kernel<<<Nn, 256>>>(adj);
    z1_kernel<<<Nn / 8, 256>>>(x, W1, b1);
    spmm_kernel<<<(Nn / BM) * KSPLIT, 128>>>(adj);    // layer 1 partials
    epilogue_kernel<<<Nn * HID / 4 / 256, 256>>>();   // -> g_h
    z2_kernel<<<Nn / 8, 256>>>(W2, b2);               // g_h -> g_zs
    spmm_kernel<<<(Nn / BM) * KSPLIT, 128>>>(adj);    // layer 2 partials
    epilogue_kernel<<<Nn * HID / 4 / 256, 256>>>();   // -> g_h
    final_kernel<<<Nn / 8, 256>>>(W3, b3, out);
}

// round 4
// speedup vs baseline: 5.6733x; 2.2368x over previous
#include <cuda_runtime.h>
#include <cuda_fp16.h>
#include <cstdint>

#define Nn     8192
#define IND    128
#define HID    32
#define BM     128
#define BN     32
#define BK     64
#define KSPLIT 8
#define KCHUNK (Nn / KSPLIT)    // 1024
#define NTILE  (KCHUNK / BK)    // 16

#define LDS_H  (BK + 8)               // 72 halves per padded row (144 B)
#define ASIZE  (BM * LDS_H * 2)       // 18432 B
#define BSIZE  (BN * LDS_H * 2)       // 4608 B

typedef unsigned long long u64;

// Scratch (static device arrays only; no allocations)
__device__ __half g_adjh[(size_t)Nn * Nn];           // fp16 adj (128 MB)
__device__ float  g_dinv[Nn];
__device__ float  g_zs[Nn * HID];                    // fp32 zs (exact self-loop term)
__device__ __half g_zshT[HID * Nn];                  // fp16 zs transposed [n][k]
__device__ float  g_h[Nn * HID];
__device__ float  g_part[(size_t)KSPLIT * Nn * HID]; // fp32 partials

// ---------------------------------------------------------------------------
__device__ __forceinline__ uint32_t smem_u32(const void* p) {
    uint32_t a;
    asm("{ .reg .u64 t; cvta.to.shared.u64 t, %1; cvt.u32.u64 %0, t; }" : "=r"(a) : "l"(p));
    return a;
}
__device__ __forceinline__ void cp16(uint32_t dst, const void* src) {
    asm volatile("cp.async.ca.shared.global [%0], [%1], 16;" :: "r"(dst), "l"(src));
}

// ---------------------------------------------------------------------------
// 1) degree + fp16 convert
// ---------------------------------------------------------------------------
__global__ __launch_bounds__(256) void degree_convert_kernel(const float* __restrict__ adj) {
    int row = blockIdx.x;
    const float4* rp = reinterpret_cast<const float4*>(adj + (size_t)row * Nn);
    uint2* hp = reinterpret_cast<uint2*>(g_adjh + (size_t)row * Nn);
    float s = 0.f;
#pragma unroll
    for (int i = threadIdx.x; i < Nn / 4; i += 256) {
        float4 v = rp[i];
        s += (v.x + v.y) + (v.z + v.w);
        __half2 a = __floats2half2_rn(v.x, v.y);
        __half2 b = __floats2half2_rn(v.z, v.w);
        uint2 w;
        w.x = *reinterpret_cast<uint32_t*>(&a);
        w.y = *reinterpret_cast<uint32_t*>(&b);
        hp[i] = w;
    }
#pragma unroll
    for (int o = 16; o; o >>= 1) s += __shfl_down_sync(0xffffffffu, s, o);
    __shared__ float ws[8];
    int lane = threadIdx.x & 31, w = threadIdx.x >> 5;
    if (lane == 0) ws[w] = s;
    __syncthreads();
    if (threadIdx.x == 0) {
        float d = 1.0f;  // self loop
#pragma unroll
        for (int i = 0; i < 8; i++) d += ws[i];
        d = fmaxf(d, 1.0f);
        g_dinv[row] = rsqrtf(d);
    }
}

// ---------------------------------------------------------------------------
// 2) zs = dinv ⊙ (x @ W1 + b1)   ; fp32 g_zs + fp16 transposed g_zshT
// ---------------------------------------------------------------------------
__global__ __launch_bounds__(256) void z1_kernel(const float* __restrict__ x,
                                                 const float* __restrict__ W1,
                                                 const float* __restrict__ b1) {
    __shared__ float Ws[IND * HID];
    __shared__ float xs[8][IND];
    int tid = threadIdx.x;
    int row0 = blockIdx.x * 8;
    for (int i = tid; i < IND * HID; i += 256) Ws[i] = W1[i];
    for (int i = tid; i < 8 * IND; i += 256)
        xs[i >> 7][i & 127] = x[(size_t)(row0 + (i >> 7)) * IND + (i & 127)];
    __syncthreads();
    int r = tid >> 5, c = tid & 31;
    float acc = b1[c];
#pragma unroll 8
    for (int k = 0; k < IND; k++) acc += xs[r][k] * Ws[k * HID + c];
    int row = row0 + r;
    float v = g_dinv[row] * acc;
    g_zs[row * HID + c] = v;
    g_zshT[(size_t)c * Nn + row] = __float2half_rn(v);
}

// ---------------------------------------------------------------------------
// 4) zs = dinv ⊙ (h @ W2 + b2)
// ---------------------------------------------------------------------------
__global__ __launch_bounds__(256) void z2_kernel(const float* __restrict__ W2,
                                                 const float* __restrict__ b2) {
    __shared__ float Ws[HID * HID];
    __shared__ float hs[8][HID];
    int tid = threadIdx.x;
    int row0 = blockIdx.x * 8;
    for (int i = tid; i < HID * HID; i += 256) Ws[i] = W2[i];
    for (int i = tid; i < 8 * HID; i += 256)
        hs[i >> 5][i & 31] = g_h[(size_t)(row0 + (i >> 5)) * HID + (i & 31)];
    __syncthreads();
    int r = tid >> 5, c = tid & 31;
    float acc = b2[c];
#pragma unroll
    for (int k = 0; k < HID; k++) acc += hs[r][k] * Ws[k * HID + c];
    int row = row0 + r;
    float v = g_dinv[row] * acc;
    g_zs[row * HID + c] = v;
    g_zshT[(size_t)c * Nn + row] = __float2half_rn(v);
}

// ---------------------------------------------------------------------------
// 3+5) partials of adjh @ zshT^T via mma.sync m16n8k16 (HMMA), cp.async pipeline.
//      grid = 64 M-tiles * KSPLIT = 512 blocks, 128 threads (4 warps).
// ---------------------------------------------------------------------------
__global__ __launch_bounds__(128) void spmm_mma_kernel() {
    __shared__ __align__(16) unsigned char smem[2 * ASIZE + 2 * BSIZE];

    const int tid  = threadIdx.x;
    const int wid  = tid >> 5;
    const int lane = tid & 31;
    const int mb   = blockIdx.x >> 3;
    const int ks   = blockIdx.x & (KSPLIT - 1);
    const int row0 = mb * BM;
    const int k0   = ks * KCHUNK;

    const uint32_t sbase = smem_u32(smem);
    const uint32_t aOff[2] = { sbase, sbase + ASIZE };
    const uint32_t bOff[2] = { sbase + 2 * ASIZE, sbase + 2 * ASIZE + BSIZE };

    // cp.async load mapping: A = 8 chunks/thread, B = 2 chunks/thread
    const int arow = tid >> 3;        // base row (A: rows arow+16i; B: rows for idx<256)
    const int ach  = (tid & 7);       // 16B chunk id (k offset = ach*8 halves)
    const __half* aSrc = g_adjh + (size_t)(row0) * Nn + k0 + ach * 8;
    const __half* bSrc = g_zshT + k0 + ach * 8;

    // mma fragment addresses (invariant parts)
    const int m0 = wid * 32;
    // A ldmatrix.x4: row = m0 + mt*16 + (lane&15), 16B chunk = (lane>>4)
    const uint32_t aFragInv = (uint32_t)((m0 + (lane & 15)) * (LDS_H * 2) + (lane >> 4) * 16);
    // B ldmatrix.x2: row = nt*8 + (lane&7), chunk = (lane>>3)&1
    const uint32_t bFragInv = (uint32_t)(((lane & 7)) * (LDS_H * 2) + ((lane >> 3) & 1) * 16);

    float c[2][4][4];
#pragma unroll
    for (int mt = 0; mt < 2; mt++)
#pragma unroll
        for (int nt = 0; nt < 4; nt++)
#pragma unroll
            for (int j = 0; j < 4; j++) c[mt][nt][j] = 0.f;

    // ---- load tile helper (as lambda via macro-ish inline) ----
    auto issue_tile = [&](int s, int t) {
        const size_t koff = (size_t)t * BK;
        const uint32_t aB = aOff[s] + arow * (LDS_H * 2) + ach * 16;
#pragma unroll
        for (int i = 0; i < 8; i++)
            cp16(aB + i * 16 * (LDS_H * 2), aSrc + ((size_t)(arow + 16 * i)) * Nn + koff);
        const uint32_t bB = bOff[s] + arow * (LDS_H * 2) + ach * 16;
#pragma unroll
        for (int i = 0; i < 2; i++)
            cp16(bB + i * 16 * (LDS_H * 2), bSrc + ((size_t)(arow + 16 * i)) * Nn + koff);
        asm volatile("cp.async.commit_group;" ::: "memory");
    };

    issue_tile(0, 0);

    for (int t = 0; t < NTILE; t++) {
        const int s = t & 1;
        if (t + 1 < NTILE) {
            issue_tile(s ^ 1, t + 1);
            asm volatile("cp.async.wait_group 1;" ::: "memory");
        } else {
            asm volatile("cp.async.wait_group 0;" ::: "memory");
        }
        __syncthreads();

        const uint32_t aT = aOff[s] + aFragInv;
        const uint32_t bT = bOff[s] + bFragInv;
#pragma unroll
        for (int kk = 0; kk < 4; kk++) {
            uint32_t a[2][4];
#pragma unroll
            for (int mt = 0; mt < 2; mt++) {
                asm volatile(
                    "ldmatrix.sync.aligned.m8n8.x4.shared.b16 {%0,%1,%2,%3}, [%4];"
                    : "=r"(a[mt][0]), "=r"(a[mt][1]), "=r"(a[mt][2]), "=r"(a[mt][3])
                    : "r"(aT + mt * 16 * (LDS_H * 2) + kk * 32));
            }
            uint32_t b[4][2];
#pragma unroll
            for (int nt = 0; nt < 4; nt++) {
                asm volatile(
                    "ldmatrix.sync.aligned.m8n8.x2.shared.b16 {%0,%1}, [%2];"
                    : "=r"(b[nt][0]), "=r"(b[nt][1])
                    : "r"(bT + nt * 8 * (LDS_H * 2) + kk * 32));
            }
#pragma unroll
            for (int mt = 0; mt < 2; mt++)
#pragma unroll
                for (int nt = 0; nt < 4; nt++) {
                    asm volatile(
                        "mma.sync.aligned.m16n8k16.row.col.f32.f16.f16.f32 "
                        "{%0,%1,%2,%3}, {%4,%5,%6,%7}, {%8,%9}, {%0,%1,%2,%3};"
                        : "+f"(c[mt][nt][0]), "+f"(c[mt][nt][1]),
                          "+f"(c[mt][nt][2]), "+f"(c[mt][nt][3])
                        : "r"(a[mt][0]), "r"(a[mt][1]), "r"(a[mt][2]), "r"(a[mt][3]),
                          "r"(b[nt][0]), "r"(b[nt][1]));
                }
        }
        __syncthreads();
    }

    // Epilogue: write partials. Lane l holds rows g=l/4 (+8), cols 2*(l%4)+{0,1}
    float* pp = g_part + (size_t)ks * Nn * HID;
    const int g  = lane >> 2;
    const int tg = lane & 3;
#pragma unroll
    for (int mt = 0; mt < 2; mt++) {
        const int rbase = row0 + m0 + mt * 16;
#pragma unroll
        for (int nt = 0; nt < 4; nt++) {
            const int col = nt * 8 + tg * 2;
            *reinterpret_cast<float2*>(&pp[(size_t)(rbase + g) * HID + col]) =
                make_float2(c[mt][nt][0], c[mt][nt][1]);
            *reinterpret_cast<float2*>(&pp[(size_t)(rbase + g + 8) * HID + col]) =
                make_float2(c[mt][nt][2], c[mt][nt][3]);
        }
    }
}

// ---------------------------------------------------------------------------
// Epilogue: h = relu(dinv ⊙ (sum_k partials + zs))
// ---------------------------------------------------------------------------
__global__ __launch_bounds__(256) void epilogue_kernel() {
    int idx4 = blockIdx.x * 256 + threadIdx.x;
    int row = (idx4 << 2) >> 5;
    float4 s = reinterpret_cast<const float4*>(g_zs)[idx4];
#pragma unroll
    for (int p = 0; p < KSPLIT; p++) {
        float4 v = reinterpret_cast<const float4*>(g_part + (size_t)p * Nn * HID)[idx4];
        s.x += v.x; s.y += v.y; s.z += v.z; s.w += v.w;
    }
    float di = g_dinv[row];
    float4 o;
    o.x = fmaxf(di * s.x, 0.f);
    o.y = fmaxf(di * s.y, 0.f);
    o.z = fmaxf(di * s.z, 0.f);
    o.w = fmaxf(di * s.w, 0.f);
    reinterpret_cast<float4*>(g_h)[idx4] = o;
}

// ---------------------------------------------------------------------------
// 6) logits[i] = h[i,:] @ W3 + b3
// ---------------------------------------------------------------------------
__global__ __launch_bounds__(256) void final_kernel(const float* __restrict__ W3,
                                                    const float* __restrict__ b3,
                                                    float* __restrict__ out) {
    int tid = threadIdx.x;
    int row = blockIdx.x * 8 + (tid >> 5);
    int c = tid & 31;
    float v = g_h[row * HID + c] * W3[c];
#pragma unroll
    for (int o = 16; o; o >>= 1) v += __shfl_down_sync(0xffffffffu, v, o);
    if (c == 0) out[row] = v + b3[0];
}

// ---------------------------------------------------------------------------
extern "C" void kernel_launch(void* const* d_in, const int* in_sizes, int n_in,
                              void* d_out, int out_size) {
    const float* x   = (const float*)d_in[0];
    const float* adj = (const float*)d_in[1];
    const float* W1  = (const float*)d_in[2];
    const float* b1  = (const float*)d_in[3];
    const float* W2  = (const float*)d_in[4];
    const float* b2  = (const float*)d_in[5];
    const float* W3  = (const float*)d_in[6];
    const float* b3  = (const float*)d_in[7];
    float* out = (float*)d_out;

    degree_convert_kernel<<<Nn, 256>>>(adj);
    z1_kernel<<<Nn / 8, 256>>>(x, W1, b1);
    spmm_mma_kernel<<<(Nn / BM) * KSPLIT, 128>>>();   // layer 1 partials
    epilogue_kernel<<<Nn * HID / 4 / 256, 256>>>();   // -> g_h
    z2_kernel<<<Nn / 8, 256>>>(W2, b2);               // g_h -> g_zs, g_zshT
    spmm_mma_kernel<<<(Nn / BM) * KSPLIT, 128>>>();   // layer 2 partials
    epilogue_kernel<<<Nn * HID / 4 / 256, 256>>>();   // -> g_h
    final_kernel<<<Nn / 8, 256>>>(W3, b3, out);
}